// round 1
// baseline (speedup 1.0000x reference)
#include <cuda_runtime.h>
#include <cuda_bf16.h>
#include <math.h>

// Sobel 3x3 (cross-correlation, zero padding) + fused magnitude:
//   out = sqrt(gx^2 + gy^2 + 1e-4), gx/gy scaled by 1/4 per reference kernels.
//
// Layout strategy (memory-bound stencil):
//  - 128x16 output tile per 256-thread block; blockDim = (128, 2).
//  - Each thread computes a VERTICAL strip of 8 rows at one column:
//    3-row register rolling => 30 LDS per 8 outputs (3.75/px).
//  - Lane -> consecutive column mapping => conflict-free LDS, coalesced STG.
//  - Shared tile 18 rows x 136 floats, filled with aligned float4 loads,
//    zero-filled halo (matches padding=1 zeros).

#define H 512
#define W 512
#define TILE_W 128
#define TILE_H 16
#define SH (TILE_H + 2)      // 18 rows
#define SW 136               // 128 + 8 pad (4 left halo incl. align, room right)
#define SW4 (SW / 4)         // 34 float4 per row

__global__ __launch_bounds__(256, 8)
void sobel_kernel(const float* __restrict__ in, float* __restrict__ out) {
    __shared__ float s[SH][SW];

    const int img = blockIdx.z;
    const int gx0 = blockIdx.x * TILE_W;
    const int gy0 = blockIdx.y * TILE_H;

    const float* __restrict__ src = in  + (size_t)img * (H * W);
    float* __restrict__       dst = out + (size_t)img * (H * W);

    const int tx  = threadIdx.x;          // 0..127
    const int ty  = threadIdx.y;          // 0..1
    const int tid = ty * 128 + tx;        // 0..255

    // -------- Load 18 x 136 tile as float4 with zero-filled halo --------
    // shared (r, c) corresponds to global (gy0 - 1 + r, gx0 - 4 + c)
    #pragma unroll
    for (int idx = tid; idx < SH * SW4; idx += 256) {
        const int r  = idx / SW4;
        const int c4 = idx - r * SW4;
        const int gr = gy0 - 1 + r;
        const int gc = gx0 - 4 + c4 * 4;

        float4 v = make_float4(0.f, 0.f, 0.f, 0.f);
        if ((unsigned)gr < (unsigned)H) {
            const float* row = src + gr * W;
            if (gc >= 0 && gc <= W - 4) {
                v = *reinterpret_cast<const float4*>(row + gc);
            } else {
                float t0 = ((unsigned)(gc + 0) < (unsigned)W) ? row[gc + 0] : 0.f;
                float t1 = ((unsigned)(gc + 1) < (unsigned)W) ? row[gc + 1] : 0.f;
                float t2 = ((unsigned)(gc + 2) < (unsigned)W) ? row[gc + 2] : 0.f;
                float t3 = ((unsigned)(gc + 3) < (unsigned)W) ? row[gc + 3] : 0.f;
                v = make_float4(t0, t1, t2, t3);
            }
        }
        *reinterpret_cast<float4*>(&s[r][c4 * 4]) = v;
    }
    __syncthreads();

    // -------- Compute: vertical strip of 8 rows at column c --------
    const int c    = 4 + tx;       // shared column of this thread's output col
    const int base = ty * 8;       // first shared-halo row index for this strip

    // rows base .. base+9 feed outputs base+0 .. base+7 (shared rows base+1..base+8
    // hold outputs; s row i maps to output row i-1)
    float a0 = s[base][c - 1],     a1 = s[base][c],     a2 = s[base][c + 1];
    float b0 = s[base + 1][c - 1], b1 = s[base + 1][c], b2 = s[base + 1][c + 1];

    const int gcol = gx0 + tx;

    #pragma unroll
    for (int j = 0; j < 8; j++) {
        const int rr = base + j + 2;
        const float c0 = s[rr][c - 1], c1 = s[rr][c], c2 = s[rr][c + 1];

        // cross-correlation with kx, ky (rows a=top, b=mid, c=bot)
        float gxv = (a0 - a2) + 2.f * (b0 - b2) + (c0 - c2);
        float gyv = (a0 - c0) + 2.f * (a1 - c1) + (a2 - c2);
        gxv *= 0.25f;
        gyv *= 0.25f;

        const float o = sqrtf(fmaf(gxv, gxv, fmaf(gyv, gyv, 1e-4f)));
        dst[(gy0 + base + j) * W + gcol] = o;

        a0 = b0; a1 = b1; a2 = b2;
        b0 = c0; b1 = c1; b2 = c2;
    }
}

extern "C" void kernel_launch(void* const* d_in, const int* in_sizes, int n_in,
                              void* d_out, int out_size) {
    (void)in_sizes; (void)n_in; (void)out_size;
    const float* x = (const float*)d_in[0];
    float* y = (float*)d_out;

    dim3 block(128, 2, 1);
    dim3 grid(W / TILE_W, H / TILE_H, 64);   // (4, 32, 64)
    sobel_kernel<<<grid, block>>>(x, y);
}

// round 2
// speedup vs baseline: 1.0525x; 1.0525x over previous
#include <cuda_runtime.h>
#include <cuda_bf16.h>
#include <math.h>

// Sobel 3x3 (zero padding) + fused magnitude, no shared memory.
//
// Each thread: 4 consecutive columns x 8 rows, straight from global float4
// loads. 3-row register rolling (top/mid/bot). Column halo via warp shuffle
// (lane-1's .w, lane+1's .x); warp-edge lanes do predicated scalar LDGs.
// Vertical re-reads (2 extra rows per 8-row strip) are L2 hits (1 MB/image
// working set vs 126 MB L2). No barriers, minimal LSU work:
// 1 LDG.128 + 1 STG.128 per 4 outputs per row.

#define H 512
#define W 512
#define ROWS 8          // rows per thread strip

__global__ __launch_bounds__(256, 8)
void sobel_kernel(const float* __restrict__ in, float* __restrict__ out) {
    const int lane = threadIdx.x;                 // 0..31
    const int wy   = threadIdx.y;                 // 0..7
    const int img  = blockIdx.z;
    const int c0   = blockIdx.x * 128 + lane * 4; // first of 4 columns
    const int r0   = (blockIdx.y * 8 + wy) * ROWS;

    const float* __restrict__ src = in  + (size_t)img * (H * W);
    float* __restrict__       dst = out + (size_t)img * (H * W);

    const bool haveL = (c0 > 0);
    const bool haveR = (c0 + 4 < W);

    float4 T, M, B;
    float tl, tr, ml, mr, bl, br;

    // Row loader: gr is warp-uniform, so the branch (and the shuffles inside)
    // are non-divergent.
    auto loadrow = [&](int gr, float4& v, float& l, float& r) {
        if ((unsigned)gr < (unsigned)H) {
            const float* __restrict__ row = src + gr * W;
            v = *reinterpret_cast<const float4*>(row + c0);
            float el = 0.f, er = 0.f;
            if (lane == 0  && haveL) el = row[c0 - 1];
            if (lane == 31 && haveR) er = row[c0 + 4];
            float sl = __shfl_up_sync(0xffffffffu, v.w, 1);
            float sr = __shfl_down_sync(0xffffffffu, v.x, 1);
            l = (lane == 0)  ? el : sl;
            r = (lane == 31) ? er : sr;
        } else {
            v = make_float4(0.f, 0.f, 0.f, 0.f);
            l = 0.f; r = 0.f;
        }
    };

    loadrow(r0 - 1, T, tl, tr);
    loadrow(r0,     M, ml, mr);

    #pragma unroll
    for (int j = 0; j < ROWS; j++) {
        loadrow(r0 + j + 1, B, bl, br);

        const float t[6] = { tl, T.x, T.y, T.z, T.w, tr };
        const float m[6] = { ml, M.x, M.y, M.z, M.w, mr };
        const float b[6] = { bl, B.x, B.y, B.z, B.w, br };

        float o[4];
        #pragma unroll
        for (int i = 0; i < 4; i++) {
            float gx = (t[i] - t[i + 2]) + 2.f * (m[i] - m[i + 2]) + (b[i] - b[i + 2]);
            float gy = (t[i] + 2.f * t[i + 1] + t[i + 2])
                     - (b[i] + 2.f * b[i + 1] + b[i + 2]);
            gx *= 0.25f;
            gy *= 0.25f;
            o[i] = sqrtf(fmaf(gx, gx, fmaf(gy, gy, 1e-4f)));
        }

        *reinterpret_cast<float4*>(dst + (size_t)(r0 + j) * W + c0) =
            make_float4(o[0], o[1], o[2], o[3]);

        T = M; tl = ml; tr = mr;
        M = B; ml = bl; mr = br;
    }
}

extern "C" void kernel_launch(void* const* d_in, const int* in_sizes, int n_in,
                              void* d_out, int out_size) {
    (void)in_sizes; (void)n_in; (void)out_size;
    const float* x = (const float*)d_in[0];
    float* y = (float*)d_out;

    dim3 block(32, 8, 1);                    // 256 threads: 128 cols x 1 strip-row each warp
    dim3 grid(W / 128, H / (8 * ROWS), 64);  // (4, 8, 64) = 2048 blocks
    sobel_kernel<<<grid, block>>>(x, y);
}

// round 4
// speedup vs baseline: 1.3007x; 1.2358x over previous
#include <cuda_runtime.h>
#include <cuda_bf16.h>
#include <math.h>

// Sobel 3x3 (zero padding) + fused magnitude, no shared memory, MLP-first.
//
// Each thread: 4 consecutive columns x 8 rows. ALL 10 input rows are loaded
// up front as independent LDG.128 (MLP ~10 per warp) before any consumption,
// trading occupancy (3 CTAs/SM) for memory-level parallelism. Column halo via
// warp shuffle; warp-edge lanes use predicated scalar LDGs issued in the same
// front batch. No barriers.

#define H 512
#define W 512
#define ROWS 8          // output rows per thread strip (needs ROWS+2 input rows)
#define NR (ROWS + 2)

__global__ __launch_bounds__(256, 3)
void sobel_kernel(const float* __restrict__ in, float* __restrict__ out) {
    const int lane = threadIdx.x;                 // 0..31
    const int wy   = threadIdx.y;                 // 0..7
    const int img  = blockIdx.z;
    const int c0   = blockIdx.x * 128 + lane * 4; // first of 4 columns
    const int r0   = (blockIdx.y * 8 + wy) * ROWS;

    const float* __restrict__ src = in  + (size_t)img * (H * W);
    float* __restrict__       dst = out + (size_t)img * (H * W);

    const bool haveL = (c0 > 0);
    const bool haveR = (c0 + 4 < W);

    // ---- Front-batched loads: 10 independent LDG.128 + edge scalars ----
    float4 v[NR];
    float  el[NR], er[NR];

    #pragma unroll
    for (int r = 0; r < NR; r++) {
        const int gr = r0 - 1 + r;
        el[r] = 0.f; er[r] = 0.f;
        if ((unsigned)gr < (unsigned)H) {
            const float* __restrict__ row = src + gr * W;
            v[r] = *reinterpret_cast<const float4*>(row + c0);
            if (lane == 0  && haveL) el[r] = row[c0 - 1];
            if (lane == 31 && haveR) er[r] = row[c0 + 4];
        } else {
            v[r] = make_float4(0.f, 0.f, 0.f, 0.f);
        }
    }

    // ---- Column halos via shuffle (warp-uniform control flow) ----
    float lh[NR], rh[NR];
    #pragma unroll
    for (int r = 0; r < NR; r++) {
        const float sl = __shfl_up_sync(0xffffffffu, v[r].w, 1);
        const float sr = __shfl_down_sync(0xffffffffu, v[r].x, 1);
        lh[r] = (lane == 0)  ? el[r] : sl;
        rh[r] = (lane == 31) ? er[r] : sr;
    }

    // ---- Compute 8 output rows, store as float4 ----
    #pragma unroll
    for (int j = 0; j < ROWS; j++) {
        const float t[6] = { lh[j],     v[j].x,     v[j].y,     v[j].z,     v[j].w,     rh[j] };
        const float m[6] = { lh[j + 1], v[j + 1].x, v[j + 1].y, v[j + 1].z, v[j + 1].w, rh[j + 1] };
        const float b[6] = { lh[j + 2], v[j + 2].x, v[j + 2].y, v[j + 2].z, v[j + 2].w, rh[j + 2] };

        float o[4];
        #pragma unroll
        for (int i = 0; i < 4; i++) {
            float gx = (t[i] - t[i + 2]) + 2.f * (m[i] - m[i + 2]) + (b[i] - b[i + 2]);
            float gy = (t[i] + 2.f * t[i + 1] + t[i + 2])
                     - (b[i] + 2.f * b[i + 1] + b[i + 2]);
            gx *= 0.25f;
            gy *= 0.25f;
            o[i] = sqrtf(fmaf(gx, gx, fmaf(gy, gy, 1e-4f)));
        }

        *reinterpret_cast<float4*>(dst + (size_t)(r0 + j) * W + c0) =
            make_float4(o[0], o[1], o[2], o[3]);
    }
}

extern "C" void kernel_launch(void* const* d_in, const int* in_sizes, int n_in,
                              void* d_out, int out_size) {
    (void)in_sizes; (void)n_in; (void)out_size;
    const float* x = (const float*)d_in[0];
    float* y = (float*)d_out;

    dim3 block(32, 8, 1);                    // 256 threads
    dim3 grid(W / 128, H / (8 * ROWS), 64);  // (4, 8, 64) = 2048 blocks
    sobel_kernel<<<grid, block>>>(x, y);
}

// round 5
// speedup vs baseline: 1.3289x; 1.0217x over previous
#include <cuda_runtime.h>
#include <cuda_bf16.h>
#include <math.h>

// Sobel 3x3 (zero padding) + fused magnitude. No shared memory.
//
// R5 changes vs R4 (issue-bound reduction):
//  - sqrt.approx.f32 (single MUFU) instead of IEEE sqrtf sequence
//  - 0.25 scaling folded: out = 0.25*sqrt(gx^2+gy^2+1.6e-3)
//  - Y-edge template specialization: interior warps have ZERO bounds checks
//  - explicit separable prefilter (q = h-diff, p = h-smooth, reused across
//    the 3 output rows each input row feeds)
// Memory structure unchanged: 4 cols x 8 rows per thread, 10 front-batched
// independent LDG.128 per thread (MLP-first), halo via warp shuffle.

#define H 512
#define W 512
#define ROWS 8
#define NR (ROWS + 2)

__device__ __forceinline__ float sqrt_approx(float x) {
    float r;
    asm("sqrt.approx.f32 %0, %1;" : "=f"(r) : "f"(x));
    return r;
}

template<bool YEDGE>
__device__ __forceinline__ void sobel_strip(const float* __restrict__ src,
                                            float* __restrict__ dst,
                                            int lane, int c0, int r0,
                                            bool haveL, bool haveR) {
    // ---- Front-batched loads: 10 independent LDG.128 (+ lane-edge scalars) ----
    float4 v[NR];
    float  el[NR], er[NR];

    #pragma unroll
    for (int r = 0; r < NR; r++) {
        const int gr = r0 - 1 + r;
        el[r] = 0.f; er[r] = 0.f;
        if (!YEDGE || (unsigned)gr < (unsigned)H) {
            const float* __restrict__ row = src + gr * W;
            v[r] = *reinterpret_cast<const float4*>(row + c0);
            if (lane == 0  && haveL) el[r] = row[c0 - 1];
            if (lane == 31 && haveR) er[r] = row[c0 + 4];
        } else {
            v[r] = make_float4(0.f, 0.f, 0.f, 0.f);
        }
    }

    // ---- Separable prefilter per input row (computed once, reused x3) ----
    // q[i] = t[i] - t[i+2]        (horizontal diff, for gx)
    // p[i] = t[i] + 2 t[i+1] + t[i+2]  (horizontal smooth, for gy)
    float pa[4], qa[4], pb[4], qb[4];

    auto prefilter = [&](int r, float* p, float* q) {
        const float sl = __shfl_up_sync(0xffffffffu, v[r].w, 1);
        const float sr = __shfl_down_sync(0xffffffffu, v[r].x, 1);
        const float t0 = (lane == 0)  ? el[r] : sl;
        const float t5 = (lane == 31) ? er[r] : sr;
        const float t1 = v[r].x, t2 = v[r].y, t3 = v[r].z, t4 = v[r].w;
        q[0] = t0 - t2; q[1] = t1 - t3; q[2] = t2 - t4; q[3] = t3 - t5;
        p[0] = fmaf(2.f, t1, t0 + t2);
        p[1] = fmaf(2.f, t2, t1 + t3);
        p[2] = fmaf(2.f, t3, t2 + t4);
        p[3] = fmaf(2.f, t4, t3 + t5);
    };

    prefilter(0, pa, qa);
    prefilter(1, pb, qb);

    #pragma unroll
    for (int j = 0; j < ROWS; j++) {
        float pc[4], qc[4];
        prefilter(j + 2, pc, qc);

        float o[4];
        #pragma unroll
        for (int i = 0; i < 4; i++) {
            // gx = q_top + 2 q_mid + q_bot ; gy = p_top - p_bot (both unscaled by 1/4)
            const float gx = fmaf(2.f, qb[i], qa[i] + qc[i]);
            const float gy = pa[i] - pc[i];
            const float m  = fmaf(gx, gx, fmaf(gy, gy, 1.6e-3f));
            o[i] = 0.25f * sqrt_approx(m);
        }
        *reinterpret_cast<float4*>(dst + (size_t)(r0 + j) * W + c0) =
            make_float4(o[0], o[1], o[2], o[3]);

        #pragma unroll
        for (int i = 0; i < 4; i++) {
            pa[i] = pb[i]; qa[i] = qb[i];
            pb[i] = pc[i]; qb[i] = qc[i];
        }
    }
}

__global__ __launch_bounds__(256, 3)
void sobel_kernel(const float* __restrict__ in, float* __restrict__ out) {
    const int lane = threadIdx.x;                 // 0..31
    const int wy   = threadIdx.y;                 // 0..7
    const int img  = blockIdx.z;
    const int c0   = blockIdx.x * 128 + lane * 4;
    const int r0   = (blockIdx.y * 8 + wy) * ROWS;

    const float* __restrict__ src = in  + (size_t)img * (H * W);
    float* __restrict__       dst = out + (size_t)img * (H * W);

    const bool haveL = (c0 > 0);
    const bool haveR = (c0 + 4 < W);

    // r0 is warp-uniform; only strips touching row 0 or row H-1 need checks.
    if (r0 != 0 && r0 + ROWS != H) {
        sobel_strip<false>(src, dst, lane, c0, r0, haveL, haveR);
    } else {
        sobel_strip<true>(src, dst, lane, c0, r0, haveL, haveR);
    }
}

extern "C" void kernel_launch(void* const* d_in, const int* in_sizes, int n_in,
                              void* d_out, int out_size) {
    (void)in_sizes; (void)n_in; (void)out_size;
    const float* x = (const float*)d_in[0];
    float* y = (float*)d_out;

    dim3 block(32, 8, 1);                    // 256 threads
    dim3 grid(W / 128, H / (8 * ROWS), 64);  // (4, 8, 64) = 2048 blocks
    sobel_kernel<<<grid, block>>>(x, y);
}

// round 6
// speedup vs baseline: 1.3909x; 1.0467x over previous
#include <cuda_runtime.h>
#include <cuda_bf16.h>
#include <math.h>

// Sobel 3x3 (zero padding) + fused magnitude. No shared memory.
//
// R6 vs R5: concurrency-first. Strip cut from 8 rows to 4 rows (6 front-
// batched LDG.128/thread instead of 10) to drop register pressure and let
// 4 CTAs/SM reside (occ ~50% vs 31.5%). Latency hiding now comes from warp
// count x MLP, not MLP alone. Output stored with evict-first hint (__stcs)
// to preserve L2 residency of input rows re-read by neighbor strips.
//  - sqrt.approx.f32, folded 0.25 scale, separable prefilter, Y-edge
//    template specialization all retained from R5.

#define H 512
#define W 512
#define ROWS 4
#define NR (ROWS + 2)

__device__ __forceinline__ float sqrt_approx(float x) {
    float r;
    asm("sqrt.approx.f32 %0, %1;" : "=f"(r) : "f"(x));
    return r;
}

template<bool YEDGE>
__device__ __forceinline__ void sobel_strip(const float* __restrict__ src,
                                            float* __restrict__ dst,
                                            int lane, int c0, int r0,
                                            bool haveL, bool haveR) {
    // ---- Front-batched loads: 6 independent LDG.128 (+ lane-edge scalars) ----
    float4 v[NR];
    float  el[NR], er[NR];

    #pragma unroll
    for (int r = 0; r < NR; r++) {
        const int gr = r0 - 1 + r;
        el[r] = 0.f; er[r] = 0.f;
        if (!YEDGE || (unsigned)gr < (unsigned)H) {
            const float* __restrict__ row = src + gr * W;
            v[r] = *reinterpret_cast<const float4*>(row + c0);
            if (lane == 0  && haveL) el[r] = row[c0 - 1];
            if (lane == 31 && haveR) er[r] = row[c0 + 4];
        } else {
            v[r] = make_float4(0.f, 0.f, 0.f, 0.f);
        }
    }

    // ---- Separable prefilter per input row (computed once, reused x3) ----
    // q[i] = t[i] - t[i+2]            (horizontal diff, for gx)
    // p[i] = t[i] + 2 t[i+1] + t[i+2] (horizontal smooth, for gy)
    float pa[4], qa[4], pb[4], qb[4];

    auto prefilter = [&](int r, float* p, float* q) {
        const float sl = __shfl_up_sync(0xffffffffu, v[r].w, 1);
        const float sr = __shfl_down_sync(0xffffffffu, v[r].x, 1);
        const float t0 = (lane == 0)  ? el[r] : sl;
        const float t5 = (lane == 31) ? er[r] : sr;
        const float t1 = v[r].x, t2 = v[r].y, t3 = v[r].z, t4 = v[r].w;
        q[0] = t0 - t2; q[1] = t1 - t3; q[2] = t2 - t4; q[3] = t3 - t5;
        p[0] = fmaf(2.f, t1, t0 + t2);
        p[1] = fmaf(2.f, t2, t1 + t3);
        p[2] = fmaf(2.f, t3, t2 + t4);
        p[3] = fmaf(2.f, t4, t3 + t5);
    };

    prefilter(0, pa, qa);
    prefilter(1, pb, qb);

    #pragma unroll
    for (int j = 0; j < ROWS; j++) {
        float pc[4], qc[4];
        prefilter(j + 2, pc, qc);

        float4 o;
        {
            float gx, gy, m;
            gx = fmaf(2.f, qb[0], qa[0] + qc[0]);
            gy = pa[0] - pc[0];
            m  = fmaf(gx, gx, fmaf(gy, gy, 1.6e-3f));
            o.x = 0.25f * sqrt_approx(m);
            gx = fmaf(2.f, qb[1], qa[1] + qc[1]);
            gy = pa[1] - pc[1];
            m  = fmaf(gx, gx, fmaf(gy, gy, 1.6e-3f));
            o.y = 0.25f * sqrt_approx(m);
            gx = fmaf(2.f, qb[2], qa[2] + qc[2]);
            gy = pa[2] - pc[2];
            m  = fmaf(gx, gx, fmaf(gy, gy, 1.6e-3f));
            o.z = 0.25f * sqrt_approx(m);
            gx = fmaf(2.f, qb[3], qa[3] + qc[3]);
            gy = pa[3] - pc[3];
            m  = fmaf(gx, gx, fmaf(gy, gy, 1.6e-3f));
            o.w = 0.25f * sqrt_approx(m);
        }
        // evict-first store: output is never re-read; keep L2 for input rows
        __stcs(reinterpret_cast<float4*>(dst + (size_t)(r0 + j) * W + c0), o);

        #pragma unroll
        for (int i = 0; i < 4; i++) {
            pa[i] = pb[i]; qa[i] = qb[i];
            pb[i] = pc[i]; qb[i] = qc[i];
        }
    }
}

__global__ __launch_bounds__(256, 4)
void sobel_kernel(const float* __restrict__ in, float* __restrict__ out) {
    const int lane = threadIdx.x;                 // 0..31
    const int wy   = threadIdx.y;                 // 0..7
    const int img  = blockIdx.z;
    const int c0   = blockIdx.x * 128 + lane * 4;
    const int r0   = (blockIdx.y * 8 + wy) * ROWS;

    const float* __restrict__ src = in  + (size_t)img * (H * W);
    float* __restrict__       dst = out + (size_t)img * (H * W);

    const bool haveL = (c0 > 0);
    const bool haveR = (c0 + 4 < W);

    // r0 is warp-uniform; only strips touching row 0 or row H-1 need checks.
    if (r0 != 0 && r0 + ROWS != H) {
        sobel_strip<false>(src, dst, lane, c0, r0, haveL, haveR);
    } else {
        sobel_strip<true>(src, dst, lane, c0, r0, haveL, haveR);
    }
}

extern "C" void kernel_launch(void* const* d_in, const int* in_sizes, int n_in,
                              void* d_out, int out_size) {
    (void)in_sizes; (void)n_in; (void)out_size;
    const float* x = (const float*)d_in[0];
    float* y = (float*)d_out;

    dim3 block(32, 8, 1);                      // 256 threads
    dim3 grid(W / 128, H / (8 * ROWS), 64);    // (4, 16, 64) = 4096 blocks
    sobel_kernel<<<grid, block>>>(x, y);
}